// round 15
// baseline (speedup 1.0000x reference)
#include <cuda_runtime.h>
#include <cstdint>

// FiniteWindowTopologicalAttention — tf32 mma.sync GEMMs + 2q-blocked attention
//   K0 : round weights -> tf32 copies    (tiny)
//   K1 : qkv = x @ w_qkv                 (tf32 mma, A rounded in-fragment)
//   K2 : windowed attention              (fp32, 2 q-rows/thread: halves LDS)
//   K3 : out = ao @ w_proj + b_proj      (tf32 mma)
//
// R15 change: attn was LDS *instruction-rate* bound (L1 94.6%, invariant to
// padding — quarter-warp phases were already pure broadcasts, no conflicts).
// Each thread now computes 2 query rows, so every K/V LDS.128 feeds two dot
// products -> LDS instruction count per window halves. CTA = 64 thr = 1 window.

#define D_MODEL 256
#define NQKV    768
#define M_TOK   262144          // 4 * 256 * 256
#define NWIN    16384           // 4 * 64 * 64

// scratch (allocation-free rule: __device__ globals)
__device__ float g_qkv   [(size_t)M_TOK * NQKV];     // 768 MB
__device__ float g_ao    [(size_t)M_TOK * D_MODEL];  // 256 MB (tf32-rounded)
__device__ float g_wqkv_r [D_MODEL * NQKV];
__device__ float g_wproj_r[D_MODEL * D_MODEL];

// ---------------- helpers -----------------------------------------------------
__device__ __forceinline__ float tf32r(float x) {
    uint32_t r;
    asm("cvt.rna.tf32.f32 %0, %1;" : "=r"(r) : "f"(x));
    return __uint_as_float(r);
}
__device__ __forceinline__ uint32_t tf32u(uint32_t x) {
    uint32_t r;
    asm("cvt.rna.tf32.f32 %0, %1;" : "=r"(r) : "f"(__uint_as_float(x)));
    return r;
}
__device__ __forceinline__ void mma_tf32(float c[4], const uint32_t a[4],
                                         const uint32_t b[2]) {
    asm volatile(
        "mma.sync.aligned.m16n8k8.row.col.f32.tf32.tf32.f32 "
        "{%0,%1,%2,%3}, {%4,%5,%6,%7}, {%8,%9}, {%0,%1,%2,%3};"
        : "+f"(c[0]), "+f"(c[1]), "+f"(c[2]), "+f"(c[3])
        : "r"(a[0]), "r"(a[1]), "r"(a[2]), "r"(a[3]), "r"(b[0]), "r"(b[1]));
}
__device__ __forceinline__ void cp16(uint32_t dst, const void* src) {
    asm volatile("cp.async.cg.shared.global [%0], [%1], 16;"
                 :: "r"(dst), "l"(src));
}

// ---------------- pre-pass kernel ---------------------------------------------
__global__ void round_w_kernel(const float* __restrict__ in,
                               float* __restrict__ out, int n)
{
    int i = blockIdx.x * blockDim.x + threadIdx.x;
    if (i < n) out[i] = tf32r(in[i]);
}

// ---------------- tf32 GEMM: C[M,N] = A[M,256] * B[256,N] (+bias) ------------
// BM=128, BN=128, BK=32. 128 threads = 4 warps (2m x 2n), warp tile 64x64.
// (unchanged from R13 — proven correct & race-free)
#define XS_F (128 * 36)          // 4608 floats
#define WS_F (32 * 136)          // 4352 floats
#define STAGE_F (XS_F + WS_F)    // 8960 floats
#define GEMM_SMEM_BYTES (2 * STAGE_F * 4)   // 71680 B

template<bool ROUND_A>
__global__ __launch_bounds__(128, 2)
void tf32_gemm_kernel(const float* __restrict__ A, const float* __restrict__ B,
                      float* __restrict__ C, const float* __restrict__ bias,
                      int N)
{
    extern __shared__ float smem[];
    const uint32_t sbase = (uint32_t)__cvta_generic_to_shared(smem);

    const int tid  = threadIdx.x;
    const int warp = tid >> 5, lane = tid & 31;
    const int wm = warp >> 1, wn = warp & 1;       // 2 x 2 warp grid, 64x64 each
    const int g  = lane >> 2, t = lane & 3;

    const size_t rowbase = (size_t)blockIdx.y * 128;
    const int    colbase = blockIdx.x * 128;

    float acc[4][8][4];
#pragma unroll
    for (int i = 0; i < 4; i++)
#pragma unroll
        for (int j = 0; j < 8; j++)
#pragma unroll
            for (int r = 0; r < 4; r++) acc[i][j][r] = 0.f;

    auto issue_tile = [&](int kt, int buf) {
        uint32_t su = sbase + (uint32_t)(buf * STAGE_F * 4);
#pragma unroll
        for (int i = 0; i < 8; i++) {
            int ch = tid + i * 128;
            int r  = ch >> 3, kg = ch & 7;
            cp16(su + (uint32_t)((r * 36 + kg * 4) * 4),
                 A + (rowbase + r) * 256 + kt * 32 + kg * 4);
        }
#pragma unroll
        for (int i = 0; i < 8; i++) {
            int ch = tid + i * 128;
            int r  = ch >> 5, c = (ch & 31) << 2;
            cp16(su + (uint32_t)((XS_F + r * 136 + c) * 4),
                 B + (size_t)(kt * 32 + r) * N + colbase + c);
        }
        asm volatile("cp.async.commit_group;");
    };

    issue_tile(0, 0);

    for (int kt = 0; kt < 8; kt++) {
        asm volatile("cp.async.wait_group 0;");
        __syncthreads();

        if (kt < 7) issue_tile(kt + 1, (kt + 1) & 1);   // overlaps compute

        const uint32_t* xs = (const uint32_t*)(smem + (kt & 1) * STAGE_F);
        const uint32_t* ws = xs + XS_F;

#pragma unroll
        for (int k8 = 0; k8 < 4; k8++) {
            const int k0 = k8 * 8;
            uint32_t a[4][4];
#pragma unroll
            for (int i = 0; i < 4; i++) {
                const int r0 = wm * 64 + i * 16;
                a[i][0] = xs[(r0 + g)     * 36 + k0 + t];
                a[i][1] = xs[(r0 + g + 8) * 36 + k0 + t];
                a[i][2] = xs[(r0 + g)     * 36 + k0 + t + 4];
                a[i][3] = xs[(r0 + g + 8) * 36 + k0 + t + 4];
                if (ROUND_A) {
                    a[i][0] = tf32u(a[i][0]); a[i][1] = tf32u(a[i][1]);
                    a[i][2] = tf32u(a[i][2]); a[i][3] = tf32u(a[i][3]);
                }
            }
            uint32_t b[8][2];
#pragma unroll
            for (int j = 0; j < 8; j++) {
                const int c0 = wn * 64 + j * 8;
                b[j][0] = ws[(k0 + t)     * 136 + c0 + g];
                b[j][1] = ws[(k0 + t + 4) * 136 + c0 + g];
            }
#pragma unroll
            for (int i = 0; i < 4; i++)
#pragma unroll
                for (int j = 0; j < 8; j++) mma_tf32(acc[i][j], a[i], b[j]);
        }
    }

#pragma unroll
    for (int i = 0; i < 4; i++) {
        const size_t m0 = rowbase + wm * 64 + i * 16 + g;
#pragma unroll
        for (int j = 0; j < 8; j++) {
            const int n0 = colbase + wn * 64 + j * 8 + t * 2;
            float2 v0 = make_float2(acc[i][j][0], acc[i][j][1]);
            float2 v1 = make_float2(acc[i][j][2], acc[i][j][3]);
            if (bias) {
                float2 bb = *(const float2*)(bias + n0);
                v0.x += bb.x; v0.y += bb.y;
                v1.x += bb.x; v1.y += bb.y;
            }
            *(float2*)(C + m0 * N + n0)       = v0;
            *(float2*)(C + (m0 + 8) * N + n0) = v1;
        }
    }
}

// ---------------- Windowed attention, 2 q-rows per thread ---------------------
// One CTA (64 threads) per 4x4 window. Thread = (head h, q-pair qp):
//   qi0 = 2*qp, qi1 = 2*qp+1  -> same qt = qp>>1, qs0 in {0,2}, qs1 = qs0+1
//   -> consecutive global rows qrow0, qrow0+1.
// Each K/V LDS.128 feeds both q-rows -> half the LDS instructions of R14.
__global__ __launch_bounds__(64)
void attn_kernel(const float* __restrict__ qkv,
                 const float* __restrict__ rpb_table,
                 float* __restrict__ ao)
{
    __shared__ float skv [16 * 512];   // [token][ k(256) | v(256) ]  32 KB
    __shared__ float srpb[49 * 8];

    const int tid = threadIdx.x;
    const int wid = blockIdx.x;
    const int b   = wid >> 12;
    const int tb  = (wid >> 6) & 63;
    const int sb_ = wid & 63;
    const int base = b * 65536 + tb * 1024 + sb_ * 4;

    for (int i = tid; i < 392; i += 64) srpb[i] = rpb_table[i];

    // stage K,V: qkv columns [256..768) for 16 tokens (2048 float4 / 64 thr)
#pragma unroll
    for (int i = 0; i < 32; i++) {
        int f = tid + i * 64;             // 0..2047 float4 chunks
        int tok = f >> 7;
        int c = (f & 127) << 2;
        int row = base + (tok >> 2) * 256 + (tok & 3);
        *(float4*)&skv[tok * 512 + c] =
            *(const float4*)(qkv + (size_t)row * NQKV + 256 + c);
    }

    const int h  = tid >> 3;              // 0..7
    const int qp = tid & 7;               // 0..7
    const int qt  = qp >> 1;
    const int qs0 = (qp & 1) * 2;         // 0 or 2
    const int qrow0 = base + qt * 256 + qs0;   // qrow1 = qrow0 + 1

    float4 qv0[8], qv1[8];
    const float4* qp0 = (const float4*)(qkv + (size_t)qrow0 * NQKV + h * 32);
    const float4* qp1 = (const float4*)(qkv + (size_t)(qrow0 + 1) * NQKV + h * 32);
#pragma unroll
    for (int u = 0; u < 8; u++) { qv0[u] = qp0[u]; qv1[u] = qp1[u]; }

    __syncthreads();

    const float scale = 0.17677669529663687f;   // 32^-0.5
    float sc0[16], sc1[16];
#pragma unroll
    for (int j = 0; j < 16; j++) {
        const float4* kp = (const float4*)&skv[j * 512 + h * 32];
        float a0 = 0.f, a1 = 0.f;
#pragma unroll
        for (int u = 0; u < 8; u++) {
            float4 kv = kp[u];
            a0 += qv0[u].x * kv.x + qv0[u].y * kv.y + qv0[u].z * kv.z + qv0[u].w * kv.w;
            a1 += qv1[u].x * kv.x + qv1[u].y * kv.y + qv1[u].z * kv.z + qv1[u].w * kv.w;
        }
        int kt = j >> 2, ks = j & 3;
        int r0 = (qt - kt + 3) * 7 + (qs0 - ks + 3);
        sc0[j] = a0 * scale + srpb[r0 * 8 + h];
        sc1[j] = a1 * scale + srpb[(r0 + 1) * 8 + h];   // qs1 = qs0+1
    }

    float m0 = sc0[0], m1 = sc1[0];
#pragma unroll
    for (int j = 1; j < 16; j++) { m0 = fmaxf(m0, sc0[j]); m1 = fmaxf(m1, sc1[j]); }
    float s0 = 0.f, s1 = 0.f;
#pragma unroll
    for (int j = 0; j < 16; j++) {
        sc0[j] = __expf(sc0[j] - m0); s0 += sc0[j];
        sc1[j] = __expf(sc1[j] - m1); s1 += sc1[j];
    }
    const float inv0 = 1.f / s0, inv1 = 1.f / s1;

    float4 o0[8], o1[8];
#pragma unroll
    for (int u = 0; u < 8; u++) {
        o0[u] = make_float4(0.f, 0.f, 0.f, 0.f);
        o1[u] = make_float4(0.f, 0.f, 0.f, 0.f);
    }
#pragma unroll
    for (int j = 0; j < 16; j++) {
        float w0 = sc0[j] * inv0, w1 = sc1[j] * inv1;
        const float4* vp = (const float4*)&skv[j * 512 + 256 + h * 32];
#pragma unroll
        for (int u = 0; u < 8; u++) {
            float4 vv = vp[u];
            o0[u].x += w0 * vv.x; o0[u].y += w0 * vv.y;
            o0[u].z += w0 * vv.z; o0[u].w += w0 * vv.w;
            o1[u].x += w1 * vv.x; o1[u].y += w1 * vv.y;
            o1[u].z += w1 * vv.z; o1[u].w += w1 * vv.w;
        }
    }

    // write tf32-rounded ao so K3 fragment loads need no cvt
    float4* op0 = (float4*)(ao + (size_t)qrow0 * D_MODEL + h * 32);
    float4* op1 = (float4*)(ao + (size_t)(qrow0 + 1) * D_MODEL + h * 32);
#pragma unroll
    for (int u = 0; u < 8; u++) {
        float4 v = o0[u];
        v.x = tf32r(v.x); v.y = tf32r(v.y); v.z = tf32r(v.z); v.w = tf32r(v.w);
        op0[u] = v;
        v = o1[u];
        v.x = tf32r(v.x); v.y = tf32r(v.y); v.z = tf32r(v.z); v.w = tf32r(v.w);
        op1[u] = v;
    }
}

// ---------------- launch ------------------------------------------------------
extern "C" void kernel_launch(void* const* d_in, const int* in_sizes, int n_in,
                              void* d_out, int out_size)
{
    const float* x      = (const float*)d_in[0];   // (4,256,256,256)
    const float* w_qkv  = (const float*)d_in[1];   // (256,768)
    const float* w_proj = (const float*)d_in[2];   // (256,256)
    const float* b_proj = (const float*)d_in[3];   // (256,)
    const float* rpb    = (const float*)d_in[4];   // (49,8)
    float* out = (float*)d_out;

    float *qkv_p, *ao_p, *wq_p, *wp_p;
    cudaGetSymbolAddress((void**)&qkv_p, g_qkv);
    cudaGetSymbolAddress((void**)&ao_p,  g_ao);
    cudaGetSymbolAddress((void**)&wq_p,  g_wqkv_r);
    cudaGetSymbolAddress((void**)&wp_p,  g_wproj_r);

    cudaFuncSetAttribute(tf32_gemm_kernel<true>,
                         cudaFuncAttributeMaxDynamicSharedMemorySize,
                         GEMM_SMEM_BYTES);
    cudaFuncSetAttribute(tf32_gemm_kernel<false>,
                         cudaFuncAttributeMaxDynamicSharedMemorySize,
                         GEMM_SMEM_BYTES);

    // pre-round weights only (x is rounded in-fragment inside K1; ao is
    // rounded by the attention epilogue)
    round_w_kernel<<<(D_MODEL * NQKV) / 256, 256>>>(w_qkv, wq_p, D_MODEL * NQKV);
    round_w_kernel<<<(D_MODEL * D_MODEL) / 256, 256>>>(w_proj, wp_p,
                                                       D_MODEL * D_MODEL);

    // K1: qkv = x @ w_qkv  (A = raw x, rounded per-fragment)
    tf32_gemm_kernel<true><<<dim3(NQKV / 128, M_TOK / 128), 128,
                             GEMM_SMEM_BYTES>>>(x, wq_p, qkv_p, nullptr, NQKV);

    // K2: attention (64 threads per window, 2 q-rows per thread)
    attn_kernel<<<NWIN, 64>>>(qkv_p, rpb, ao_p);

    // K3: out = ao @ w_proj + b_proj  (A = ao, already tf32)
    tf32_gemm_kernel<false><<<dim3(D_MODEL / 128, M_TOK / 128), 128,
                              GEMM_SMEM_BYTES>>>(ao_p, wp_p, out, b_proj,
                                                 D_MODEL);
}